// round 4
// baseline (speedup 1.0000x reference)
// R3: identical to R2 submission — two consecutive broker-level container
// failures carry no kernel signal; resubmitting for attributable results.
#include <cuda_runtime.h>
#include <cuda_fp16.h>
#include <cstdint>
#include <cstddef>

// Problem dims
#define T_  512
#define B_  128
#define E_  300
#define H_  128
#define G4  512            // 4*H
#define KP  320            // K padded to multiple of 32
#define M_  (T_*B_)        // 65536 rows (t-major: m = t*B + b)
#define N_  1024           // both directions' 4H concatenated
#define FC1_ 256
#define C_  5

// ---------------- device scratch (module-load allocated, no cudaMalloc) ----------------
__device__ __half g_xh[(size_t)M_ * KP];      // fp16 padded activations  (~40 MB)
__device__ __half g_wcat[(size_t)N_ * KP];    // fp16 padded input weights (both dirs)
__device__ float  g_xg[(size_t)M_ * N_];      // input-gate preactivations (~256 MB)
__device__ float  g_hf[(size_t)T_ * B_ * H_]; // forward hidden states  [t][b][u]
__device__ float  g_hb[(size_t)T_ * B_ * H_]; // backward hidden states [t][b][u]

// ---------------- prep: fp32 -> fp16 padded ----------------
__global__ void prep_x(const float* __restrict__ x) {
    int m = blockIdx.x * 2 + (threadIdx.x >= KP); // m = t*B + b
    int t = m >> 7;
    int b = m & 127;
    int e = threadIdx.x >= KP ? threadIdx.x - KP : threadIdx.x; // 0..319
    float v = (e < E_) ? x[((size_t)b * T_ + t) * E_ + e] : 0.f;
    g_xh[(size_t)m * KP + e] = __float2half_rn(v);
}

__global__ void prep_w(const float* __restrict__ wf, const float* __restrict__ wb) {
    int n = blockIdx.x;            // 0..1023
    int e = threadIdx.x;
    float v = 0.f;
    if (e < E_) v = (n < G4) ? wf[(size_t)n * E_ + e] : wb[(size_t)(n - G4) * E_ + e];
    g_wcat[(size_t)n * KP + e] = __float2half_rn(v);
}

// ---------------- input GEMM: xg[m][n] = sum_k xh[m][k] * wcat[n][k] ----------------
#define BM 128
#define BN 64
#define BK 32
#define SSTR (BK + 8)   // padded smem stride (halves)

__global__ __launch_bounds__(256) void gemm_hmma() {
    __shared__ __half As[2][BM][SSTR];
    __shared__ __half Bs[2][BN][SSTR];

    int tid  = threadIdx.x;
    int wid  = tid >> 5;
    int lane = tid & 31;
    int wm   = wid >> 1;       // 0..3  (32-row warp tile)
    int wn   = wid & 1;        // 0..1  (32-col warp tile)
    int bm   = blockIdx.y * BM;
    int bn   = blockIdx.x * BN;

    float acc[2][4][4];
#pragma unroll
    for (int i = 0; i < 2; i++)
#pragma unroll
        for (int j = 0; j < 4; j++)
#pragma unroll
            for (int k = 0; k < 4; k++) acc[i][j][k] = 0.f;

    int ar = tid >> 2;            // 0..63
    int ac = (tid & 3) * 8;       // 0,8,16,24

    uint4 ra0, ra1, rb0;
    // preload tile 0
    {
        ra0 = *(const uint4*)&g_xh[(size_t)(bm + ar)      * KP + ac];
        ra1 = *(const uint4*)&g_xh[(size_t)(bm + 64 + ar) * KP + ac];
        rb0 = *(const uint4*)&g_wcat[(size_t)(bn + ar)    * KP + ac];
        *(uint4*)&As[0][ar][ac]      = ra0;
        *(uint4*)&As[0][64 + ar][ac] = ra1;
        *(uint4*)&Bs[0][ar][ac]      = rb0;
    }
    __syncthreads();

    const int NIT = KP / BK;      // 10
    for (int it = 0; it < NIT; ++it) {
        int cur = it & 1;
        bool pf = (it + 1 < NIT);
        if (pf) {
            int k0 = (it + 1) * BK;
            ra0 = *(const uint4*)&g_xh[(size_t)(bm + ar)      * KP + k0 + ac];
            ra1 = *(const uint4*)&g_xh[(size_t)(bm + 64 + ar) * KP + k0 + ac];
            rb0 = *(const uint4*)&g_wcat[(size_t)(bn + ar)    * KP + k0 + ac];
        }
#pragma unroll
        for (int kk = 0; kk < 2; ++kk) {
            uint32_t a[2][4], bf[4][2];
#pragma unroll
            for (int mf = 0; mf < 2; ++mf) {
                int row = wm * 32 + mf * 16 + (lane & 15);
                int ko  = kk * 16 + (lane >> 4) * 8;
                unsigned sa = (unsigned)__cvta_generic_to_shared(&As[cur][row][ko]);
                asm volatile("ldmatrix.sync.aligned.m8n8.x4.shared.b16 {%0,%1,%2,%3}, [%4];"
                             : "=r"(a[mf][0]), "=r"(a[mf][1]), "=r"(a[mf][2]), "=r"(a[mf][3])
                             : "r"(sa));
            }
#pragma unroll
            for (int nf = 0; nf < 4; ++nf) {
                int row = wn * 32 + nf * 8 + (lane & 7);
                int ko  = kk * 16 + ((lane >> 3) & 1) * 8;
                unsigned sb = (unsigned)__cvta_generic_to_shared(&Bs[cur][row][ko]);
                asm volatile("ldmatrix.sync.aligned.m8n8.x2.shared.b16 {%0,%1}, [%2];"
                             : "=r"(bf[nf][0]), "=r"(bf[nf][1])
                             : "r"(sb));
            }
#pragma unroll
            for (int mf = 0; mf < 2; ++mf)
#pragma unroll
                for (int nf = 0; nf < 4; ++nf)
                    asm volatile(
                        "mma.sync.aligned.m16n8k16.row.col.f32.f16.f16.f32 "
                        "{%0,%1,%2,%3},{%4,%5,%6,%7},{%8,%9},{%0,%1,%2,%3};"
                        : "+f"(acc[mf][nf][0]), "+f"(acc[mf][nf][1]),
                          "+f"(acc[mf][nf][2]), "+f"(acc[mf][nf][3])
                        : "r"(a[mf][0]), "r"(a[mf][1]), "r"(a[mf][2]), "r"(a[mf][3]),
                          "r"(bf[nf][0]), "r"(bf[nf][1]));
        }
        __syncthreads();
        if (pf) {
            int nxt = 1 - cur;
            *(uint4*)&As[nxt][ar][ac]      = ra0;
            *(uint4*)&As[nxt][64 + ar][ac] = ra1;
            *(uint4*)&Bs[nxt][ar][ac]      = rb0;
        }
        __syncthreads();
    }

    // epilogue
#pragma unroll
    for (int mf = 0; mf < 2; ++mf)
#pragma unroll
        for (int nf = 0; nf < 4; ++nf) {
            int r = bm + wm * 32 + mf * 16 + (lane >> 2);
            int c = bn + wn * 32 + nf * 8 + (lane & 3) * 2;
            *(float2*)&g_xg[(size_t)r * N_ + c]       = make_float2(acc[mf][nf][0], acc[mf][nf][1]);
            *(float2*)&g_xg[(size_t)(r + 8) * N_ + c] = make_float2(acc[mf][nf][2], acc[mf][nf][3]);
        }
}

// ---------------- LSTM scan (both directions), fp32 exact ----------------
__device__ __forceinline__ void fma2(unsigned long long& d, unsigned long long a, unsigned long long b) {
    asm("fma.rn.f32x2 %0, %1, %2, %0;" : "+l"(d) : "l"(a), "l"(b));
}
__device__ __forceinline__ float sigf(float x) { return 1.f / (1.f + __expf(-x)); }

#define SCAN_SMEM (131072 + 256*4 + 1024*4)

__global__ __launch_bounds__(512, 1) void lstm_scan(
    const float* __restrict__ Whh_f, const float* __restrict__ Whh_b,
    const float* __restrict__ bih_f, const float* __restrict__ bhh_f,
    const float* __restrict__ bih_b, const float* __restrict__ bhh_b) {
    extern __shared__ float smem[];
    unsigned long long* sW = (unsigned long long*)smem;  // [32][512] transposed hi-half of Whh (k pairs)
    float* sh = smem + 32768;                            // [2][128] current h (2 batches)
    float* sg = sh + 256;                                // [2][512] gate preacts

    int j    = threadIdx.x;        // gate row 0..511
    int dir  = blockIdx.x >> 6;    // 0 fwd, 1 bwd
    int pair = blockIdx.x & 63;
    int b0   = pair * 2;

    const float* Whh = dir ? Whh_b : Whh_f;
    const unsigned long long* wrow = (const unsigned long long*)(Whh + (size_t)j * H_);
    unsigned long long wreg[32];                         // k = 0..63 in registers (f32x2 pairs)
#pragma unroll
    for (int p = 0; p < 32; p++) wreg[p] = wrow[p];
#pragma unroll
    for (int p = 0; p < 32; p++) sW[p * 512 + j] = wrow[32 + p];   // k = 64..127 transposed in smem

    float bias = dir ? (bih_b[j] + bhh_b[j]) : (bih_f[j] + bhh_f[j]);
    if (j < 256) sh[j] = 0.f;
    float cst = 0.f;                                     // c-state (threads j<256: u=j&127, batch=j>>7)
    float* hout = dir ? g_hb : g_hf;
    __syncthreads();

    for (int s = 0; s < T_; ++s) {
        int tt = dir ? (T_ - 1 - s) : s;
        const float* xgp = g_xg + ((size_t)tt * B_ + b0) * N_ + dir * G4 + j;
        float x0 = xgp[0];
        float x1 = xgp[N_];

        unsigned long long acc0 = 0ull, acc1 = 0ull;
        const unsigned long long* h0 = (const unsigned long long*)sh;
        const unsigned long long* h1 = h0 + 64;
#pragma unroll
        for (int p = 0; p < 32; p++) { fma2(acc0, wreg[p], h0[p]); fma2(acc1, wreg[p], h1[p]); }
#pragma unroll
        for (int p = 0; p < 32; p++) {
            unsigned long long w = sW[p * 512 + j];
            fma2(acc0, w, h0[32 + p]); fma2(acc1, w, h1[32 + p]);
        }
        union { unsigned long long u; float2 f; } u0, u1;
        u0.u = acc0; u1.u = acc1;
        float g0 = u0.f.x + u0.f.y + x0 + bias;
        float g1 = u1.f.x + u1.f.y + x1 + bias;
        sg[j] = g0; sg[512 + j] = g1;
        __syncthreads();

        if (j < 256) {
            int u = j & 127, bs = j >> 7;
            const float* gB = sg + bs * 512;
            float ii = sigf(gB[u]);
            float ff = sigf(gB[128 + u]);
            float cc = tanhf(gB[256 + u]);
            float oo = sigf(gB[384 + u]);
            cst = ff * cst + ii * cc;
            float hn = oo * tanhf(cst);
            sh[bs * 128 + u] = hn;
            hout[((size_t)tt * B_ + b0 + bs) * H_ + u] = hn;
        }
        __syncthreads();
    }
}

// ---------------- attention pooling + MLP head (fused, one CTA per batch) ----------------
__global__ __launch_bounds__(256) void attn_mlp(
    const float* __restrict__ attn_w, const float* __restrict__ attn_b,
    const float* __restrict__ fc1_w, const float* __restrict__ fc1_b,
    const float* __restrict__ fc2_w, const float* __restrict__ fc2_b,
    float* __restrict__ out) {
    __shared__ float aw[256];
    __shared__ float sl[512];
    __shared__ float red[256];
    __shared__ float sp[256];
    __shared__ float sh1[256];

    int b = blockIdx.x, tid = threadIdx.x;
    aw[tid] = attn_w[tid];
    __syncthreads();
    float ab = attn_b[0];

    // logits[t] = <lstm_out[b,t,:], attn_w> + ab
#pragma unroll
    for (int r = 0; r < 2; r++) {
        int t = tid + r * 256;
        const float4* pf = (const float4*)&g_hf[((size_t)t * B_ + b) * H_];
        const float4* pb = (const float4*)&g_hb[((size_t)t * B_ + b) * H_];
        const float4* wf = (const float4*)aw;
        const float4* wb = (const float4*)(aw + 128);
        float acc = 0.f;
#pragma unroll 8
        for (int q = 0; q < 32; q++) {
            float4 a = pf[q]; float4 w = wf[q];
            acc += a.x * w.x + a.y * w.y + a.z * w.z + a.w * w.w;
        }
#pragma unroll 8
        for (int q = 0; q < 32; q++) {
            float4 a = pb[q]; float4 w = wb[q];
            acc += a.x * w.x + a.y * w.y + a.z * w.z + a.w * w.w;
        }
        sl[t] = acc + ab;
    }
    __syncthreads();

    // softmax over T
    red[tid] = fmaxf(sl[tid], sl[tid + 256]);
    __syncthreads();
    for (int st = 128; st > 0; st >>= 1) {
        if (tid < st) red[tid] = fmaxf(red[tid], red[tid + st]);
        __syncthreads();
    }
    float mx = red[0];
    __syncthreads();
    float e0 = __expf(sl[tid] - mx), e1 = __expf(sl[tid + 256] - mx);
    sl[tid] = e0; sl[tid + 256] = e1;
    red[tid] = e0 + e1;
    __syncthreads();
    for (int st = 128; st > 0; st >>= 1) {
        if (tid < st) red[tid] += red[tid + st];
        __syncthreads();
    }
    float inv = 1.f / red[0];
    __syncthreads();

    // pooled[j] = sum_t w[t] * lstm_out[b,t,j]
    {
        const float* src = (tid < 128) ? g_hf : g_hb;
        int u = tid & 127;
        float a0 = 0, a1 = 0, a2 = 0, a3 = 0;
        for (int t = 0; t < 512; t += 4) {
            a0 += sl[t    ] * src[((size_t)(t    ) * B_ + b) * H_ + u];
            a1 += sl[t + 1] * src[((size_t)(t + 1) * B_ + b) * H_ + u];
            a2 += sl[t + 2] * src[((size_t)(t + 2) * B_ + b) * H_ + u];
            a3 += sl[t + 3] * src[((size_t)(t + 3) * B_ + b) * H_ + u];
        }
        sp[tid] = (a0 + a1 + a2 + a3) * inv;
    }
    __syncthreads();

    // fc1 + relu
    {
        const float4* w = (const float4*)&fc1_w[(size_t)tid * 256];
        const float4* p = (const float4*)sp;
        float acc = fc1_b[tid];
#pragma unroll 8
        for (int q = 0; q < 64; q++) {
            float4 a = p[q]; float4 ww = w[q];
            acc += a.x * ww.x + a.y * ww.y + a.z * ww.z + a.w * ww.w;
        }
        sh1[tid] = fmaxf(acc, 0.f);
    }
    __syncthreads();

    // fc2: 5 outputs, one warp each
    if (tid < 160) {
        int c = tid >> 5, lane = tid & 31;
        float acc = 0.f;
        for (int q = lane; q < 256; q += 32) acc += sh1[q] * fc2_w[(size_t)c * 256 + q];
#pragma unroll
        for (int o = 16; o > 0; o >>= 1) acc += __shfl_down_sync(0xffffffffu, acc, o);
        if (lane == 0) out[b * C_ + c] = acc + fc2_b[c];
    }
}

// ---------------- launch ----------------
extern "C" void kernel_launch(void* const* d_in, const int* in_sizes, int n_in,
                              void* d_out, int out_size) {
    const float* x      = (const float*)d_in[0];
    const float* Wih_f  = (const float*)d_in[1];
    const float* Whh_f  = (const float*)d_in[2];
    const float* bih_f  = (const float*)d_in[3];
    const float* bhh_f  = (const float*)d_in[4];
    const float* Wih_b  = (const float*)d_in[5];
    const float* Whh_b  = (const float*)d_in[6];
    const float* bih_b  = (const float*)d_in[7];
    const float* bhh_b  = (const float*)d_in[8];
    const float* attn_w = (const float*)d_in[9];
    const float* attn_b = (const float*)d_in[10];
    const float* fc1_w  = (const float*)d_in[11];
    const float* fc1_b  = (const float*)d_in[12];
    const float* fc2_w  = (const float*)d_in[13];
    const float* fc2_b  = (const float*)d_in[14];
    float* out = (float*)d_out;

    prep_x<<<M_ / 2, 2 * KP>>>(x);
    prep_w<<<N_, KP>>>(Wih_f, Wih_b);
    gemm_hmma<<<dim3(N_ / BN, M_ / BM), 256>>>();

    cudaFuncSetAttribute(lstm_scan, cudaFuncAttributeMaxDynamicSharedMemorySize, SCAN_SMEM);
    lstm_scan<<<128, 512, SCAN_SMEM>>>(Whh_f, Whh_b, bih_f, bhh_f, bih_b, bhh_b);

    attn_mlp<<<B_, 256>>>(attn_w, attn_b, fc1_w, fc1_b, fc2_w, fc2_b, out);
}

// round 5
// speedup vs baseline: 1.0137x; 1.0137x over previous
// R5: scan rewrite — permuted gate rows + shfl gate exchange, 1 barrier/step,
// double-buffered h, fast tanh/sigmoid; g_xg in fp16 with bias folded into GEMM.
#include <cuda_runtime.h>
#include <cuda_fp16.h>
#include <cstdint>
#include <cstddef>

// Problem dims
#define T_  512
#define B_  128
#define E_  300
#define H_  128
#define G4  512            // 4*H
#define KP  320            // K padded to multiple of 32
#define M_  (T_*B_)        // 65536 rows (t-major: m = t*B + b)
#define N_  1024           // both directions' 4H concatenated
#define FC1_ 256
#define C_  5

// ---------------- device scratch ----------------
__device__ __half g_xh[(size_t)M_ * KP];      // fp16 padded activations  (~40 MB)
__device__ __half g_wcat[(size_t)N_ * KP];    // fp16 padded input weights (both dirs, PERMUTED rows)
__device__ __half g_xg[(size_t)M_ * N_];      // fp16 gate preacts incl. bias (~128 MB), PERMUTED cols
__device__ float  g_hf[(size_t)T_ * B_ * H_]; // forward hidden states  [t][b][u]
__device__ float  g_hb[(size_t)T_ * B_ * H_]; // backward hidden states [t][b][u]

// Gate-row permutation: scan thread j owns gate (j&3) of unit (j>>2).
// perm(j) = (j&3)*128 + (j>>2)  maps thread/col index -> original gate row.

// ---------------- prep: fp32 -> fp16 padded ----------------
__global__ void prep_x(const float* __restrict__ x) {
    int m = blockIdx.x * 2 + (threadIdx.x >= KP); // m = t*B + b
    int t = m >> 7;
    int b = m & 127;
    int e = threadIdx.x >= KP ? threadIdx.x - KP : threadIdx.x; // 0..319
    float v = (e < E_) ? x[((size_t)b * T_ + t) * E_ + e] : 0.f;
    g_xh[(size_t)m * KP + e] = __float2half_rn(v);
}

__global__ void prep_w(const float* __restrict__ wf, const float* __restrict__ wb) {
    int n = blockIdx.x;            // 0..1023 (output col, permuted)
    int e = threadIdx.x;
    int nn  = n & 511;
    int src = (nn & 3) * 128 + (nn >> 2);     // original gate row
    float v = 0.f;
    if (e < E_) v = (n < G4) ? wf[(size_t)src * E_ + e] : wb[(size_t)src * E_ + e];
    g_wcat[(size_t)n * KP + e] = __float2half_rn(v);
}

// ---------------- input GEMM: xg[m][n] = sum_k xh[m][k]*wcat[n][k] + bias[n] ----------------
#define BM 128
#define BN 64
#define BK 32
#define SSTR (BK + 8)

__global__ __launch_bounds__(256) void gemm_hmma(
    const float* __restrict__ bih_f, const float* __restrict__ bhh_f,
    const float* __restrict__ bih_b, const float* __restrict__ bhh_b) {
    __shared__ __half As[2][BM][SSTR];
    __shared__ __half Bs[2][BN][SSTR];

    int tid  = threadIdx.x;
    int wid  = tid >> 5;
    int lane = tid & 31;
    int wm   = wid >> 1;
    int wn   = wid & 1;
    int bm   = blockIdx.y * BM;
    int bn   = blockIdx.x * BN;

    float acc[2][4][4];
#pragma unroll
    for (int i = 0; i < 2; i++)
#pragma unroll
        for (int j = 0; j < 4; j++)
#pragma unroll
            for (int k = 0; k < 4; k++) acc[i][j][k] = 0.f;

    int ar = tid >> 2;
    int ac = (tid & 3) * 8;

    uint4 ra0, ra1, rb0;
    {
        ra0 = *(const uint4*)&g_xh[(size_t)(bm + ar)      * KP + ac];
        ra1 = *(const uint4*)&g_xh[(size_t)(bm + 64 + ar) * KP + ac];
        rb0 = *(const uint4*)&g_wcat[(size_t)(bn + ar)    * KP + ac];
        *(uint4*)&As[0][ar][ac]      = ra0;
        *(uint4*)&As[0][64 + ar][ac] = ra1;
        *(uint4*)&Bs[0][ar][ac]      = rb0;
    }
    __syncthreads();

    const int NIT = KP / BK;      // 10
    for (int it = 0; it < NIT; ++it) {
        int cur = it & 1;
        bool pf = (it + 1 < NIT);
        if (pf) {
            int k0 = (it + 1) * BK;
            ra0 = *(const uint4*)&g_xh[(size_t)(bm + ar)      * KP + k0 + ac];
            ra1 = *(const uint4*)&g_xh[(size_t)(bm + 64 + ar) * KP + k0 + ac];
            rb0 = *(const uint4*)&g_wcat[(size_t)(bn + ar)    * KP + k0 + ac];
        }
#pragma unroll
        for (int kk = 0; kk < 2; ++kk) {
            uint32_t a[2][4], bf[4][2];
#pragma unroll
            for (int mf = 0; mf < 2; ++mf) {
                int row = wm * 32 + mf * 16 + (lane & 15);
                int ko  = kk * 16 + (lane >> 4) * 8;
                unsigned sa = (unsigned)__cvta_generic_to_shared(&As[cur][row][ko]);
                asm volatile("ldmatrix.sync.aligned.m8n8.x4.shared.b16 {%0,%1,%2,%3}, [%4];"
                             : "=r"(a[mf][0]), "=r"(a[mf][1]), "=r"(a[mf][2]), "=r"(a[mf][3])
                             : "r"(sa));
            }
#pragma unroll
            for (int nf = 0; nf < 4; ++nf) {
                int row = wn * 32 + nf * 8 + (lane & 7);
                int ko  = kk * 16 + ((lane >> 3) & 1) * 8;
                unsigned sb = (unsigned)__cvta_generic_to_shared(&Bs[cur][row][ko]);
                asm volatile("ldmatrix.sync.aligned.m8n8.x2.shared.b16 {%0,%1}, [%2];"
                             : "=r"(bf[nf][0]), "=r"(bf[nf][1])
                             : "r"(sb));
            }
#pragma unroll
            for (int mf = 0; mf < 2; ++mf)
#pragma unroll
                for (int nf = 0; nf < 4; ++nf)
                    asm volatile(
                        "mma.sync.aligned.m16n8k16.row.col.f32.f16.f16.f32 "
                        "{%0,%1,%2,%3},{%4,%5,%6,%7},{%8,%9},{%0,%1,%2,%3};"
                        : "+f"(acc[mf][nf][0]), "+f"(acc[mf][nf][1]),
                          "+f"(acc[mf][nf][2]), "+f"(acc[mf][nf][3])
                        : "r"(a[mf][0]), "r"(a[mf][1]), "r"(a[mf][2]), "r"(a[mf][3]),
                          "r"(bf[nf][0]), "r"(bf[nf][1]));
        }
        __syncthreads();
        if (pf) {
            int nxt = 1 - cur;
            *(uint4*)&As[nxt][ar][ac]      = ra0;
            *(uint4*)&As[nxt][64 + ar][ac] = ra1;
            *(uint4*)&Bs[nxt][ar][ac]      = rb0;
        }
        __syncthreads();
    }

    // epilogue: add bias (permuted col -> original gate row), convert to fp16
    float bb[4][2];
#pragma unroll
    for (int nf = 0; nf < 4; ++nf) {
#pragma unroll
        for (int h = 0; h < 2; ++h) {
            int col = bn + wn * 32 + nf * 8 + (lane & 3) * 2 + h;
            int nn  = col & 511;
            int src = (nn & 3) * 128 + (nn >> 2);
            bb[nf][h] = (col < G4) ? (bih_f[src] + bhh_f[src])
                                   : (bih_b[src] + bhh_b[src]);
        }
    }
#pragma unroll
    for (int mf = 0; mf < 2; ++mf)
#pragma unroll
        for (int nf = 0; nf < 4; ++nf) {
            int r = bm + wm * 32 + mf * 16 + (lane >> 2);
            int c = bn + wn * 32 + nf * 8 + (lane & 3) * 2;
            __half2 v0 = __floats2half2_rn(acc[mf][nf][0] + bb[nf][0], acc[mf][nf][1] + bb[nf][1]);
            __half2 v1 = __floats2half2_rn(acc[mf][nf][2] + bb[nf][0], acc[mf][nf][3] + bb[nf][1]);
            *(__half2*)&g_xg[(size_t)r * N_ + c]       = v0;
            *(__half2*)&g_xg[(size_t)(r + 8) * N_ + c] = v1;
        }
}

// ---------------- LSTM scan ----------------
__device__ __forceinline__ void fma2(unsigned long long& d, unsigned long long a, unsigned long long b) {
    asm("fma.rn.f32x2 %0, %1, %2, %0;" : "+l"(d) : "l"(a), "l"(b));
}
__device__ __forceinline__ float sigf(float x) {
    return __fdividef(1.f, 1.f + __expf(-x));
}
__device__ __forceinline__ float tanh_fast(float x) {
    return 1.f - 2.f * __fdividef(1.f, __expf(2.f * x) + 1.f);
}

#define SCAN_SMEM (131072 + 2 * 256 * 4)

__global__ __launch_bounds__(512, 1) void lstm_scan(
    const float* __restrict__ Whh_f, const float* __restrict__ Whh_b) {
    extern __shared__ float smem[];
    unsigned long long* sW = (unsigned long long*)smem;  // [32][512] hi-half of Whh, transposed
    float* shbuf = smem + 32768;                         // [2][2*128] double-buffered h

    int j   = threadIdx.x;        // permuted gate-row index 0..511
    int q   = j & 3;              // 0=i 1=f 2=g 3=o
    int u   = j >> 2;             // unit 0..127
    int dir = blockIdx.x >> 6;
    int b0  = (blockIdx.x & 63) * 2;

    const float* Whh = dir ? Whh_b : Whh_f;
    int gr = q * 128 + u;                                // original gate row
    const unsigned long long* wrow = (const unsigned long long*)(Whh + (size_t)gr * H_);
    unsigned long long wreg[32];                         // k=0..63 in registers
#pragma unroll
    for (int p = 0; p < 32; p++) wreg[p] = wrow[p];
#pragma unroll
    for (int p = 0; p < 32; p++) sW[p * 512 + j] = wrow[32 + p]; // k=64..127 in smem

    if (j < 256) shbuf[j] = 0.f;                         // buffer 0 = h at step 0
    float c0 = 0.f, c1 = 0.f;                            // c-state (valid on q==0 lanes)
    float* hout = dir ? g_hb : g_hf;
    const __half* xbase = g_xg + dir * G4 + j;
    __syncthreads();

    for (int s = 0; s < T_; ++s) {
        int tt = dir ? (T_ - 1 - s) : s;
        const __half* xp = xbase + (size_t)(tt * B_ + b0) * N_;
        float x0 = __half2float(xp[0]);
        float x1 = __half2float(xp[N_]);

        const unsigned long long* h0 = (const unsigned long long*)(shbuf + (s & 1) * 256);
        const unsigned long long* h1 = h0 + 64;
        unsigned long long acc0 = 0ull, acc1 = 0ull;
#pragma unroll
        for (int p = 0; p < 32; p++) { fma2(acc0, wreg[p], h0[p]); fma2(acc1, wreg[p], h1[p]); }
#pragma unroll
        for (int p = 0; p < 32; p++) {
            unsigned long long w = sW[p * 512 + j];
            fma2(acc0, w, h0[32 + p]); fma2(acc1, w, h1[32 + p]);
        }
        union { unsigned long long uu; float2 f; } u0, u1;
        u0.uu = acc0; u1.uu = acc1;
        float g0 = u0.f.x + u0.f.y + x0;
        float g1 = u1.f.x + u1.f.y + x1;

        // activation per role; gate exchange via shfl within 4-lane groups
        float a0 = (q == 2) ? tanh_fast(g0) : sigf(g0);
        float a1 = (q == 2) ? tanh_fast(g1) : sigf(g1);
        float r2_0 = __shfl_xor_sync(0xffffffffu, a0, 2);   // q0<-tanh(g), q1<-sig(o)
        float r2_1 = __shfl_xor_sync(0xffffffffu, a1, 2);
        float r1a0 = __shfl_xor_sync(0xffffffffu, a0, 2 ^ 3); // placeholder avoided below
        // q0 <- sig(f) from q1:
        r1a0 = __shfl_xor_sync(0xffffffffu, a0, 1);
        float r1a1 = __shfl_xor_sync(0xffffffffu, a1, 1);
        // q0 <- sig(o) (q1's r2):
        float r1b0 = __shfl_xor_sync(0xffffffffu, r2_0, 1);
        float r1b1 = __shfl_xor_sync(0xffffffffu, r2_1, 1);

        float* shn = shbuf + ((s & 1) ^ 1) * 256;
        if (q == 0) {
            c0 = r1a0 * c0 + a0 * r2_0;                  // sig(f)*c + sig(i)*tanh(g)
            c1 = r1a1 * c1 + a1 * r2_1;
            float hh0 = r1b0 * tanh_fast(c0);            // sig(o)*tanh(c)
            float hh1 = r1b1 * tanh_fast(c1);
            shn[u] = hh0; shn[128 + u] = hh1;
            hout[((size_t)tt * B_ + b0)     * H_ + u] = hh0;
            hout[((size_t)tt * B_ + b0 + 1) * H_ + u] = hh1;
        }
        __syncthreads();
    }
}

// ---------------- attention pooling + MLP head ----------------
__global__ __launch_bounds__(256) void attn_mlp(
    const float* __restrict__ attn_w, const float* __restrict__ attn_b,
    const float* __restrict__ fc1_w, const float* __restrict__ fc1_b,
    const float* __restrict__ fc2_w, const float* __restrict__ fc2_b,
    float* __restrict__ out) {
    __shared__ float aw[256];
    __shared__ float sl[512];
    __shared__ float red[256];
    __shared__ float sp[256];
    __shared__ float sh1[256];

    int b = blockIdx.x, tid = threadIdx.x;
    aw[tid] = attn_w[tid];
    __syncthreads();
    float ab = attn_b[0];

#pragma unroll
    for (int r = 0; r < 2; r++) {
        int t = tid + r * 256;
        const float4* pf = (const float4*)&g_hf[((size_t)t * B_ + b) * H_];
        const float4* pb = (const float4*)&g_hb[((size_t)t * B_ + b) * H_];
        const float4* wf = (const float4*)aw;
        const float4* wb = (const float4*)(aw + 128);
        float acc = 0.f;
#pragma unroll 8
        for (int qq = 0; qq < 32; qq++) {
            float4 a = pf[qq]; float4 w = wf[qq];
            acc += a.x * w.x + a.y * w.y + a.z * w.z + a.w * w.w;
        }
#pragma unroll 8
        for (int qq = 0; qq < 32; qq++) {
            float4 a = pb[qq]; float4 w = wb[qq];
            acc += a.x * w.x + a.y * w.y + a.z * w.z + a.w * w.w;
        }
        sl[t] = acc + ab;
    }
    __syncthreads();

    red[tid] = fmaxf(sl[tid], sl[tid + 256]);
    __syncthreads();
    for (int st = 128; st > 0; st >>= 1) {
        if (tid < st) red[tid] = fmaxf(red[tid], red[tid + st]);
        __syncthreads();
    }
    float mx = red[0];
    __syncthreads();
    float e0 = __expf(sl[tid] - mx), e1 = __expf(sl[tid + 256] - mx);
    sl[tid] = e0; sl[tid + 256] = e1;
    red[tid] = e0 + e1;
    __syncthreads();
    for (int st = 128; st > 0; st >>= 1) {
        if (tid < st) red[tid] += red[tid + st];
        __syncthreads();
    }
    float inv = 1.f / red[0];
    __syncthreads();

    {
        const float* src = (tid < 128) ? g_hf : g_hb;
        int u = tid & 127;
        float a0 = 0, a1 = 0, a2 = 0, a3 = 0;
        for (int t = 0; t < 512; t += 4) {
            a0 += sl[t    ] * src[((size_t)(t    ) * B_ + b) * H_ + u];
            a1 += sl[t + 1] * src[((size_t)(t + 1) * B_ + b) * H_ + u];
            a2 += sl[t + 2] * src[((size_t)(t + 2) * B_ + b) * H_ + u];
            a3 += sl[t + 3] * src[((size_t)(t + 3) * B_ + b) * H_ + u];
        }
        sp[tid] = (a0 + a1 + a2 + a3) * inv;
    }
    __syncthreads();

    {
        const float4* w = (const float4*)&fc1_w[(size_t)tid * 256];
        const float4* p = (const float4*)sp;
        float acc = fc1_b[tid];
#pragma unroll 8
        for (int qq = 0; qq < 64; qq++) {
            float4 a = p[qq]; float4 ww = w[qq];
            acc += a.x * ww.x + a.y * ww.y + a.z * ww.z + a.w * ww.w;
        }
        sh1[tid] = fmaxf(acc, 0.f);
    }
    __syncthreads();

    if (tid < 160) {
        int c = tid >> 5, lane = tid & 31;
        float acc = 0.f;
        for (int qq = lane; qq < 256; qq += 32) acc += sh1[qq] * fc2_w[(size_t)c * 256 + qq];
#pragma unroll
        for (int o = 16; o > 0; o >>= 1) acc += __shfl_down_sync(0xffffffffu, acc, o);
        if (lane == 0) out[b * C_ + c] = acc + fc2_b[c];
    }
}

// ---------------- launch ----------------
extern "C" void kernel_launch(void* const* d_in, const int* in_sizes, int n_in,
                              void* d_out, int out_size) {
    const float* x      = (const float*)d_in[0];
    const float* Wih_f  = (const float*)d_in[1];
    const float* Whh_f  = (const float*)d_in[2];
    const float* bih_f  = (const float*)d_in[3];
    const float* bhh_f  = (const float*)d_in[4];
    const float* Wih_b  = (const float*)d_in[5];
    const float* Whh_b  = (const float*)d_in[6];
    const float* bih_b  = (const float*)d_in[7];
    const float* bhh_b  = (const float*)d_in[8];
    const float* attn_w = (const float*)d_in[9];
    const float* attn_b = (const float*)d_in[10];
    const float* fc1_w  = (const float*)d_in[11];
    const float* fc1_b  = (const float*)d_in[12];
    const float* fc2_w  = (const float*)d_in[13];
    const float* fc2_b  = (const float*)d_in[14];
    float* out = (float*)d_out;

    prep_x<<<M_ / 2, 2 * KP>>>(x);
    prep_w<<<N_, KP>>>(Wih_f, Wih_b);
    gemm_hmma<<<dim3(N_ / BN, M_ / BM), 256>>>(bih_f, bhh_f, bih_b, bhh_b);

    cudaFuncSetAttribute(lstm_scan, cudaFuncAttributeMaxDynamicSharedMemorySize, SCAN_SMEM);
    lstm_scan<<<128, 512, SCAN_SMEM>>>(Whh_f, Whh_b);

    attn_mlp<<<B_, 256>>>(attn_w, attn_b, fc1_w, fc1_b, fc2_w, fc2_b, out);
}

// round 8
// speedup vs baseline: 1.0681x; 1.0537x over previous
// R7: resubmit of R6 (broker flake — design never executed).
// Tensor-core LSTM recurrence — W in register fragments, h via ldmatrix,
// x preacts as accumulator init, shfl gate exchange, tanh.approx activations.
#include <cuda_runtime.h>
#include <cuda_fp16.h>
#include <cstdint>
#include <cstddef>

#define T_  512
#define B_  128
#define E_  300
#define H_  128
#define G4  512
#define KP  320
#define M_  (T_*B_)
#define N_  1024
#define FC1_ 256
#define C_  5

__device__ __half g_xh[(size_t)M_ * KP];
__device__ __half g_wcat[(size_t)N_ * KP];    // permuted rows
__device__ __half g_xg[(size_t)M_ * N_];      // fp16 preacts + bias, permuted cols
__device__ float  g_hf[(size_t)T_ * B_ * H_];
__device__ float  g_hb[(size_t)T_ * B_ * H_];

// ---------------- prep ----------------
__global__ void prep_x(const float* __restrict__ x) {
    int m = blockIdx.x * 2 + (threadIdx.x >= KP);
    int t = m >> 7;
    int b = m & 127;
    int e = threadIdx.x >= KP ? threadIdx.x - KP : threadIdx.x;
    float v = (e < E_) ? x[((size_t)b * T_ + t) * E_ + e] : 0.f;
    g_xh[(size_t)m * KP + e] = __float2half_rn(v);
}

__global__ void prep_w(const float* __restrict__ wf, const float* __restrict__ wb) {
    int n = blockIdx.x;
    int e = threadIdx.x;
    int nn  = n & 511;
    int src = (nn & 3) * 128 + (nn >> 2);
    float v = 0.f;
    if (e < E_) v = (n < G4) ? wf[(size_t)src * E_ + e] : wb[(size_t)src * E_ + e];
    g_wcat[(size_t)n * KP + e] = __float2half_rn(v);
}

// ---------------- input GEMM ----------------
#define BM 128
#define BN 64
#define BK 32
#define SSTR (BK + 8)

__global__ __launch_bounds__(256) void gemm_hmma(
    const float* __restrict__ bih_f, const float* __restrict__ bhh_f,
    const float* __restrict__ bih_b, const float* __restrict__ bhh_b) {
    __shared__ __half As[2][BM][SSTR];
    __shared__ __half Bs[2][BN][SSTR];

    int tid  = threadIdx.x;
    int wid  = tid >> 5;
    int lane = tid & 31;
    int wm   = wid >> 1;
    int wn   = wid & 1;
    int bm   = blockIdx.y * BM;
    int bn   = blockIdx.x * BN;

    float acc[2][4][4];
#pragma unroll
    for (int i = 0; i < 2; i++)
#pragma unroll
        for (int j = 0; j < 4; j++)
#pragma unroll
            for (int k = 0; k < 4; k++) acc[i][j][k] = 0.f;

    int ar = tid >> 2;
    int ac = (tid & 3) * 8;

    uint4 ra0, ra1, rb0;
    {
        ra0 = *(const uint4*)&g_xh[(size_t)(bm + ar)      * KP + ac];
        ra1 = *(const uint4*)&g_xh[(size_t)(bm + 64 + ar) * KP + ac];
        rb0 = *(const uint4*)&g_wcat[(size_t)(bn + ar)    * KP + ac];
        *(uint4*)&As[0][ar][ac]      = ra0;
        *(uint4*)&As[0][64 + ar][ac] = ra1;
        *(uint4*)&Bs[0][ar][ac]      = rb0;
    }
    __syncthreads();

    const int NIT = KP / BK;
    for (int it = 0; it < NIT; ++it) {
        int cur = it & 1;
        bool pf = (it + 1 < NIT);
        if (pf) {
            int k0 = (it + 1) * BK;
            ra0 = *(const uint4*)&g_xh[(size_t)(bm + ar)      * KP + k0 + ac];
            ra1 = *(const uint4*)&g_xh[(size_t)(bm + 64 + ar) * KP + k0 + ac];
            rb0 = *(const uint4*)&g_wcat[(size_t)(bn + ar)    * KP + k0 + ac];
        }
#pragma unroll
        for (int kk = 0; kk < 2; ++kk) {
            uint32_t a[2][4], bf[4][2];
#pragma unroll
            for (int mf = 0; mf < 2; ++mf) {
                int row = wm * 32 + mf * 16 + (lane & 15);
                int ko  = kk * 16 + (lane >> 4) * 8;
                unsigned sa = (unsigned)__cvta_generic_to_shared(&As[cur][row][ko]);
                asm volatile("ldmatrix.sync.aligned.m8n8.x4.shared.b16 {%0,%1,%2,%3}, [%4];"
                             : "=r"(a[mf][0]), "=r"(a[mf][1]), "=r"(a[mf][2]), "=r"(a[mf][3])
                             : "r"(sa));
            }
#pragma unroll
            for (int nf = 0; nf < 4; ++nf) {
                int row = wn * 32 + nf * 8 + (lane & 7);
                int ko  = kk * 16 + ((lane >> 3) & 1) * 8;
                unsigned sb = (unsigned)__cvta_generic_to_shared(&Bs[cur][row][ko]);
                asm volatile("ldmatrix.sync.aligned.m8n8.x2.shared.b16 {%0,%1}, [%2];"
                             : "=r"(bf[nf][0]), "=r"(bf[nf][1])
                             : "r"(sb));
            }
#pragma unroll
            for (int mf = 0; mf < 2; ++mf)
#pragma unroll
                for (int nf = 0; nf < 4; ++nf)
                    asm volatile(
                        "mma.sync.aligned.m16n8k16.row.col.f32.f16.f16.f32 "
                        "{%0,%1,%2,%3},{%4,%5,%6,%7},{%8,%9},{%0,%1,%2,%3};"
                        : "+f"(acc[mf][nf][0]), "+f"(acc[mf][nf][1]),
                          "+f"(acc[mf][nf][2]), "+f"(acc[mf][nf][3])
                        : "r"(a[mf][0]), "r"(a[mf][1]), "r"(a[mf][2]), "r"(a[mf][3]),
                          "r"(bf[nf][0]), "r"(bf[nf][1]));
        }
        __syncthreads();
        if (pf) {
            int nxt = 1 - cur;
            *(uint4*)&As[nxt][ar][ac]      = ra0;
            *(uint4*)&As[nxt][64 + ar][ac] = ra1;
            *(uint4*)&Bs[nxt][ar][ac]      = rb0;
        }
        __syncthreads();
    }

    float bb[4][2];
#pragma unroll
    for (int nf = 0; nf < 4; ++nf) {
#pragma unroll
        for (int h = 0; h < 2; ++h) {
            int col = bn + wn * 32 + nf * 8 + (lane & 3) * 2 + h;
            int nn  = col & 511;
            int src = (nn & 3) * 128 + (nn >> 2);
            bb[nf][h] = (col < G4) ? (bih_f[src] + bhh_f[src])
                                   : (bih_b[src] + bhh_b[src]);
        }
    }
#pragma unroll
    for (int mf = 0; mf < 2; ++mf)
#pragma unroll
        for (int nf = 0; nf < 4; ++nf) {
            int r = bm + wm * 32 + mf * 16 + (lane >> 2);
            int c = bn + wn * 32 + nf * 8 + (lane & 3) * 2;
            __half2 v0 = __floats2half2_rn(acc[mf][nf][0] + bb[nf][0], acc[mf][nf][1] + bb[nf][1]);
            __half2 v1 = __floats2half2_rn(acc[mf][nf][2] + bb[nf][0], acc[mf][nf][3] + bb[nf][1]);
            *(__half2*)&g_xg[(size_t)r * N_ + c]       = v0;
            *(__half2*)&g_xg[(size_t)(r + 8) * N_ + c] = v1;
        }
}

// ---------------- tensor-core LSTM scan ----------------
__device__ __forceinline__ float tanh_t(float x) {
    float r; asm("tanh.approx.f32 %0, %1;" : "=f"(r) : "f"(x)); return r;
}
__device__ __forceinline__ float sig_t(float x) {
    return fmaf(tanh_t(0.5f * x), 0.5f, 0.5f);
}

#define HSTR 136

__global__ __launch_bounds__(512, 1) void lstm_scan_mma(
    const float* __restrict__ Whh_f, const float* __restrict__ Whh_b) {
    __shared__ __align__(16) __half sh[2][16][HSTR];

    int tid = threadIdx.x;
    int w   = tid >> 5;
    int l   = tid & 31;
    int c   = l & 3;
    int rg  = l >> 2;
    int dir = blockIdx.x >> 3;
    int b0  = (blockIdx.x & 7) * 16;
    const float* Whh = dir ? Whh_b : Whh_f;
    float* hout = dir ? g_hb : g_hf;
    int n0w = w * 32;

    uint32_t bfr[4][8][2];
#pragma unroll
    for (int nt = 0; nt < 4; nt++) {
        int n    = n0w + nt * 8 + rg;
        int orig = (n & 3) * 128 + (n >> 2);
        const float* wr = Whh + (size_t)orig * H_;
#pragma unroll
        for (int kt = 0; kt < 8; kt++) {
            int k = kt * 16 + c * 2;
            float2 lo = *(const float2*)&wr[k];
            float2 hi = *(const float2*)&wr[k + 8];
            __half2 hlo = __floats2half2_rn(lo.x, lo.y);
            __half2 hhi = __floats2half2_rn(hi.x, hi.y);
            bfr[nt][kt][0] = *(uint32_t*)&hlo;
            bfr[nt][kt][1] = *(uint32_t*)&hhi;
        }
    }

    for (int i = tid; i < 2 * 16 * HSTR; i += 512) ((__half*)sh)[i] = __float2half(0.f);

    int erow = rg + ((c & 1) ? 8 : 0);

    uint32_t xr[4][2];
    {
        int tt = dir ? (T_ - 1) : 0;
        const __half* xp = g_xg + ((size_t)tt * B_ + b0) * N_ + dir * G4;
#pragma unroll
        for (int nt = 0; nt < 4; nt++) {
            int n = n0w + nt * 8 + c * 2;
            xr[nt][0] = *(const uint32_t*)&xp[(size_t)rg * N_ + n];
            xr[nt][1] = *(const uint32_t*)&xp[(size_t)(rg + 8) * N_ + n];
        }
    }

    float cst[4] = {0.f, 0.f, 0.f, 0.f};
    __syncthreads();

    for (int s = 0; s < T_; ++s) {
        int tt = dir ? (T_ - 1 - s) : s;

        float d[4][4];
#pragma unroll
        for (int nt = 0; nt < 4; nt++) {
            float2 lo = __half22float2(*(__half2*)&xr[nt][0]);
            float2 hi = __half22float2(*(__half2*)&xr[nt][1]);
            d[nt][0] = lo.x; d[nt][1] = lo.y; d[nt][2] = hi.x; d[nt][3] = hi.y;
        }

#pragma unroll
        for (int kc = 0; kc < 2; kc++) {
            uint32_t afr[4][4];
#pragma unroll
            for (int kt = 0; kt < 4; kt++) {
                int k0  = (kc * 4 + kt) * 16 + ((l & 16) ? 8 : 0);
                int row = l & 15;
                unsigned sa = (unsigned)__cvta_generic_to_shared(&sh[s & 1][row][k0]);
                asm volatile("ldmatrix.sync.aligned.m8n8.x4.shared.b16 {%0,%1,%2,%3}, [%4];"
                             : "=r"(afr[kt][0]), "=r"(afr[kt][1]), "=r"(afr[kt][2]), "=r"(afr[kt][3])
                             : "r"(sa));
            }
#pragma unroll
            for (int nt = 0; nt < 4; nt++)
#pragma unroll
                for (int kt = 0; kt < 4; kt++)
                    asm volatile(
                        "mma.sync.aligned.m16n8k16.row.col.f32.f16.f16.f32 "
                        "{%0,%1,%2,%3},{%4,%5,%6,%7},{%8,%9},{%0,%1,%2,%3};"
                        : "+f"(d[nt][0]), "+f"(d[nt][1]), "+f"(d[nt][2]), "+f"(d[nt][3])
                        : "r"(afr[kt][0]), "r"(afr[kt][1]), "r"(afr[kt][2]), "r"(afr[kt][3]),
                          "r"(bfr[nt][kc * 4 + kt][0]), "r"(bfr[nt][kc * 4 + kt][1]));
        }

        if (s + 1 < T_) {
            int tn = dir ? (T_ - 2 - s) : (s + 1);
            const __half* xp = g_xg + ((size_t)tn * B_ + b0) * N_ + dir * G4;
#pragma unroll
            for (int nt = 0; nt < 4; nt++) {
                int n = n0w + nt * 8 + c * 2;
                xr[nt][0] = *(const uint32_t*)&xp[(size_t)rg * N_ + n];
                xr[nt][1] = *(const uint32_t*)&xp[(size_t)(rg + 8) * N_ + n];
            }
        }

#pragma unroll
        for (int nt = 0; nt < 4; nt++) {
            float sendA = (c & 1) ? d[nt][0] : d[nt][2];
            float sendB = (c & 1) ? d[nt][1] : d[nt][3];
            float recvA = __shfl_xor_sync(0xffffffffu, sendA, 1);
            float recvB = __shfl_xor_sync(0xffffffffu, sendB, 1);
            float gi = (c & 1) ? recvA : d[nt][0];
            float gf = (c & 1) ? recvB : d[nt][1];
            float gg = (c & 1) ? d[nt][2] : recvA;
            float go = (c & 1) ? d[nt][3] : recvB;
            float si = sig_t(gi), sf = sig_t(gf), tg = tanh_t(gg), so = sig_t(go);
            float cn = fmaf(sf, cst[nt], si * tg);
            cst[nt] = cn;
            float hh = so * tanh_t(cn);
            int u = w * 8 + nt * 2 + (c >> 1);
            sh[(s + 1) & 1][erow][u] = __float2half_rn(hh);
            hout[((size_t)tt * B_ + b0 + erow) * H_ + u] = hh;
        }
        __syncthreads();
    }
}

// ---------------- attention pooling + MLP head ----------------
__global__ __launch_bounds__(256) void attn_mlp(
    const float* __restrict__ attn_w, const float* __restrict__ attn_b,
    const float* __restrict__ fc1_w, const float* __restrict__ fc1_b,
    const float* __restrict__ fc2_w, const float* __restrict__ fc2_b,
    float* __restrict__ out) {
    __shared__ float aw[256];
    __shared__ float sl[512];
    __shared__ float red[256];
    __shared__ float sp[256];
    __shared__ float sh1[256];

    int b = blockIdx.x, tid = threadIdx.x;
    aw[tid] = attn_w[tid];
    __syncthreads();
    float ab = attn_b[0];

#pragma unroll
    for (int r = 0; r < 2; r++) {
        int t = tid + r * 256;
        const float4* pf = (const float4*)&g_hf[((size_t)t * B_ + b) * H_];
        const float4* pb = (const float4*)&g_hb[((size_t)t * B_ + b) * H_];
        const float4* wf = (const float4*)aw;
        const float4* wb = (const float4*)(aw + 128);
        float acc = 0.f;
#pragma unroll 8
        for (int qq = 0; qq < 32; qq++) {
            float4 a = pf[qq]; float4 w = wf[qq];
            acc += a.x * w.x + a.y * w.y + a.z * w.z + a.w * w.w;
        }
#pragma unroll 8
        for (int qq = 0; qq < 32; qq++) {
            float4 a = pb[qq]; float4 w = wb[qq];
            acc += a.x * w.x + a.y * w.y + a.z * w.z + a.w * w.w;
        }
        sl[t] = acc + ab;
    }
    __syncthreads();

    red[tid] = fmaxf(sl[tid], sl[tid + 256]);
    __syncthreads();
    for (int st = 128; st > 0; st >>= 1) {
        if (tid < st) red[tid] = fmaxf(red[tid], red[tid + st]);
        __syncthreads();
    }
    float mx = red[0];
    __syncthreads();
    float e0 = __expf(sl[tid] - mx), e1 = __expf(sl[tid + 256] - mx);
    sl[tid] = e0; sl[tid + 256] = e1;
    red[tid] = e0 + e1;
    __syncthreads();
    for (int st = 128; st > 0; st >>= 1) {
        if (tid < st) red[tid] += red[tid + st];
        __syncthreads();
    }
    float inv = 1.f / red[0];
    __syncthreads();

    {
        const float* src = (tid < 128) ? g_hf : g_hb;
        int u = tid & 127;
        float a0 = 0, a1 = 0, a2 = 0, a3 = 0;
        for (int t = 0; t < 512; t += 4) {
            a0 += sl[t    ] * src[((size_t)(t    ) * B_ + b) * H_ + u];
            a1 += sl[t + 1] * src[((size_t)(t + 1) * B_ + b) * H_ + u];
            a2 += sl[t + 2] * src[((size_t)(t + 2) * B_ + b) * H_ + u];
            a3 += sl[t + 3] * src[((size_t)(t + 3) * B_ + b) * H_ + u];
        }
        sp[tid] = (a0 + a1 + a2 + a3) * inv;
    }
    __syncthreads();

    {
        const float4* w = (const float4*)&fc1_w[(size_t)tid * 256];
        const float4* p = (const float4*)sp;
        float acc = fc1_b[tid];
#pragma unroll 8
        for (int qq = 0; qq < 64; qq++) {
            float4 a = p[qq]; float4 ww = w[qq];
            acc += a.x * ww.x + a.y * ww.y + a.z * ww.z + a.w * ww.w;
        }
        sh1[tid] = fmaxf(acc, 0.f);
    }
    __syncthreads();

    if (tid < 160) {
        int cc = tid >> 5, lane = tid & 31;
        float acc = 0.f;
        for (int qq = lane; qq < 256; qq += 32) acc += sh1[qq] * fc2_w[(size_t)cc * 256 + qq];
#pragma unroll
        for (int o = 16; o > 0; o >>= 1) acc += __shfl_down_sync(0xffffffffu, acc, o);
        if (lane == 0) out[b * C_ + cc] = acc + fc2_b[cc];
    }
}

// ---------------- launch ----------------
extern "C" void kernel_launch(void* const* d_in, const int* in_sizes, int n_in,
                              void* d_out, int out_size) {
    const float* x      = (const float*)d_in[0];
    const float* Wih_f  = (const float*)d_in[1];
    const float* Whh_f  = (const float*)d_in[2];
    const float* bih_f  = (const float*)d_in[3];
    const float* bhh_f  = (const float*)d_in[4];
    const float* Wih_b  = (const float*)d_in[5];
    const float* Whh_b  = (const float*)d_in[6];
    const float* bih_b  = (const float*)d_in[7];
    const float* bhh_b  = (const float*)d_in[8];
    const float* attn_w = (const float*)d_in[9];
    const float* attn_b = (const float*)d_in[10];
    const float* fc1_w  = (const float*)d_in[11];
    const float* fc1_b  = (const float*)d_in[12];
    const float* fc2_w  = (const float*)d_in[13];
    const float* fc2_b  = (const float*)d_in[14];
    float* out = (float*)d_out;

    prep_x<<<M_ / 2, 2 * KP>>>(x);
    prep_w<<<N_, KP>>>(Wih_f, Wih_b);
    gemm_hmma<<<dim3(N_ / BN, M_ / BM), 256>>>(bih_f, bhh_f, bih_b, bhh_b);

    lstm_scan_mma<<<16, 512>>>(Whh_f, Whh_b);

    attn_mlp<<<B_, 256>>>(attn_w, attn_b, fc1_w, fc1_b, fc2_w, fc2_b, out);
}

// round 10
// speedup vs baseline: 1.5771x; 1.4766x over previous
// R10: resubmit of R9 (broker flake — design never executed; fragment math re-audited).
// Scan re-orientation — batch on n (n8), gates on m; 32 CTAs; W in A-frags;
// h via ldmatrix.x2.trans from [128][8] smem; g_xg transposed to [gate][t*B+b].
#include <cuda_runtime.h>
#include <cuda_fp16.h>
#include <cstdint>
#include <cstddef>

#define T_  512
#define B_  128
#define E_  300
#define H_  128
#define G4  512
#define KP  320
#define M_  (T_*B_)
#define N_  1024
#define FC1_ 256
#define C_  5

__device__ __half g_xh[(size_t)M_ * KP];
__device__ __half g_wcat[(size_t)N_ * KP];    // permuted rows
__device__ __half g_xg[(size_t)N_ * M_];      // fp16 preacts+bias, layout [n_perm][t*B+b]
__device__ float  g_hf[(size_t)T_ * B_ * H_];
__device__ float  g_hb[(size_t)T_ * B_ * H_];

// permutation: p in [0,512): tau=p>>4, r=p&15, gate=((r>>3)<<1)|(r&1),
// unit = tau*4 + ((r>>1)&3), original row o = gate*128 + unit.
__host__ __device__ __forceinline__ int perm_src(int p) {
    int r = p & 15;
    int g = ((r >> 3) << 1) | (r & 1);
    int u = (p >> 4) * 4 + ((r >> 1) & 3);
    return g * 128 + u;
}

// ---------------- prep ----------------
__global__ void prep_x(const float* __restrict__ x) {
    int m = blockIdx.x * 2 + (threadIdx.x >= KP);
    int t = m >> 7;
    int b = m & 127;
    int e = threadIdx.x >= KP ? threadIdx.x - KP : threadIdx.x;
    float v = (e < E_) ? x[((size_t)b * T_ + t) * E_ + e] : 0.f;
    g_xh[(size_t)m * KP + e] = __float2half_rn(v);
}

__global__ void prep_w(const float* __restrict__ wf, const float* __restrict__ wb) {
    int n = blockIdx.x;
    int e = threadIdx.x;
    int src = perm_src(n & 511);
    float v = 0.f;
    if (e < E_) v = (n < G4) ? wf[(size_t)src * E_ + e] : wb[(size_t)src * E_ + e];
    g_wcat[(size_t)n * KP + e] = __float2half_rn(v);
}

// ---------------- input GEMM ----------------
#define BM 128
#define BN 64
#define BK 32
#define SSTR (BK + 8)

__global__ __launch_bounds__(256) void gemm_hmma(
    const float* __restrict__ bih_f, const float* __restrict__ bhh_f,
    const float* __restrict__ bih_b, const float* __restrict__ bhh_b) {
    __shared__ __half As[2][BM][SSTR];
    __shared__ __half Bs[2][BN][SSTR];

    int tid  = threadIdx.x;
    int wid  = tid >> 5;
    int lane = tid & 31;
    int wm   = wid >> 1;
    int wn   = wid & 1;
    int bm   = blockIdx.y * BM;
    int bn   = blockIdx.x * BN;

    float acc[2][4][4];
#pragma unroll
    for (int i = 0; i < 2; i++)
#pragma unroll
        for (int j = 0; j < 4; j++)
#pragma unroll
            for (int k = 0; k < 4; k++) acc[i][j][k] = 0.f;

    int ar = tid >> 2;
    int ac = (tid & 3) * 8;

    uint4 ra0, ra1, rb0;
    {
        ra0 = *(const uint4*)&g_xh[(size_t)(bm + ar)      * KP + ac];
        ra1 = *(const uint4*)&g_xh[(size_t)(bm + 64 + ar) * KP + ac];
        rb0 = *(const uint4*)&g_wcat[(size_t)(bn + ar)    * KP + ac];
        *(uint4*)&As[0][ar][ac]      = ra0;
        *(uint4*)&As[0][64 + ar][ac] = ra1;
        *(uint4*)&Bs[0][ar][ac]      = rb0;
    }
    __syncthreads();

    const int NIT = KP / BK;
    for (int it = 0; it < NIT; ++it) {
        int cur = it & 1;
        bool pf = (it + 1 < NIT);
        if (pf) {
            int k0 = (it + 1) * BK;
            ra0 = *(const uint4*)&g_xh[(size_t)(bm + ar)      * KP + k0 + ac];
            ra1 = *(const uint4*)&g_xh[(size_t)(bm + 64 + ar) * KP + k0 + ac];
            rb0 = *(const uint4*)&g_wcat[(size_t)(bn + ar)    * KP + k0 + ac];
        }
#pragma unroll
        for (int kk = 0; kk < 2; ++kk) {
            uint32_t a[2][4], bf[4][2];
#pragma unroll
            for (int mf = 0; mf < 2; ++mf) {
                int row = wm * 32 + mf * 16 + (lane & 15);
                int ko  = kk * 16 + (lane >> 4) * 8;
                unsigned sa = (unsigned)__cvta_generic_to_shared(&As[cur][row][ko]);
                asm volatile("ldmatrix.sync.aligned.m8n8.x4.shared.b16 {%0,%1,%2,%3}, [%4];"
                             : "=r"(a[mf][0]), "=r"(a[mf][1]), "=r"(a[mf][2]), "=r"(a[mf][3])
                             : "r"(sa));
            }
#pragma unroll
            for (int nf = 0; nf < 4; ++nf) {
                int row = wn * 32 + nf * 8 + (lane & 7);
                int ko  = kk * 16 + ((lane >> 3) & 1) * 8;
                unsigned sb = (unsigned)__cvta_generic_to_shared(&Bs[cur][row][ko]);
                asm volatile("ldmatrix.sync.aligned.m8n8.x2.shared.b16 {%0,%1}, [%2];"
                             : "=r"(bf[nf][0]), "=r"(bf[nf][1])
                             : "r"(sb));
            }
#pragma unroll
            for (int mf = 0; mf < 2; ++mf)
#pragma unroll
                for (int nf = 0; nf < 4; ++nf)
                    asm volatile(
                        "mma.sync.aligned.m16n8k16.row.col.f32.f16.f16.f32 "
                        "{%0,%1,%2,%3},{%4,%5,%6,%7},{%8,%9},{%0,%1,%2,%3};"
                        : "+f"(acc[mf][nf][0]), "+f"(acc[mf][nf][1]),
                          "+f"(acc[mf][nf][2]), "+f"(acc[mf][nf][3])
                        : "r"(a[mf][0]), "r"(a[mf][1]), "r"(a[mf][2]), "r"(a[mf][3]),
                          "r"(bf[nf][0]), "r"(bf[nf][1]));
        }
        __syncthreads();
        if (pf) {
            int nxt = 1 - cur;
            *(uint4*)&As[nxt][ar][ac]      = ra0;
            *(uint4*)&As[nxt][64 + ar][ac] = ra1;
            *(uint4*)&Bs[nxt][ar][ac]      = rb0;
        }
        __syncthreads();
    }

    // epilogue: bias add, write transposed [n][m] as fp16
    float bb[4][2];
#pragma unroll
    for (int nf = 0; nf < 4; ++nf) {
#pragma unroll
        for (int h = 0; h < 2; ++h) {
            int col = bn + wn * 32 + nf * 8 + (lane & 3) * 2 + h;
            int src = perm_src(col & 511);
            bb[nf][h] = (col < G4) ? (bih_f[src] + bhh_f[src])
                                   : (bih_b[src] + bhh_b[src]);
        }
    }
#pragma unroll
    for (int mf = 0; mf < 2; ++mf)
#pragma unroll
        for (int nf = 0; nf < 4; ++nf) {
            int r = bm + wm * 32 + mf * 16 + (lane >> 2);
            int c = bn + wn * 32 + nf * 8 + (lane & 3) * 2;
            g_xg[(size_t)c       * M_ + r]     = __float2half_rn(acc[mf][nf][0] + bb[nf][0]);
            g_xg[(size_t)(c + 1) * M_ + r]     = __float2half_rn(acc[mf][nf][1] + bb[nf][1]);
            g_xg[(size_t)c       * M_ + r + 8] = __float2half_rn(acc[mf][nf][2] + bb[nf][0]);
            g_xg[(size_t)(c + 1) * M_ + r + 8] = __float2half_rn(acc[mf][nf][3] + bb[nf][1]);
        }
}

// ---------------- tensor-core LSTM scan (batch on n) ----------------
__device__ __forceinline__ float tanh_t(float x) {
    float r; asm("tanh.approx.f32 %0, %1;" : "=f"(r) : "f"(x)); return r;
}
__device__ __forceinline__ float sig_t(float x) {
    return fmaf(tanh_t(0.5f * x), 0.5f, 0.5f);
}

#define NB 8   // batches per CTA

__global__ __launch_bounds__(512, 1) void lstm_scan_mma(
    const float* __restrict__ Whh_f, const float* __restrict__ Whh_b) {
    __shared__ __align__(16) __half sh[2][H_][NB];   // [buf][unit(k)][batch(n)]

    int tid = threadIdx.x;
    int w   = tid >> 5;            // warp 0..15 -> gate rows w*32..w*32+31 (permuted)
    int l   = tid & 31;
    int c   = l & 3;
    int rg  = l >> 2;
    int dir = blockIdx.x >> 4;
    int b0  = (blockIdx.x & 15) * NB;
    const float* Whh = dir ? Whh_b : Whh_f;
    float* hout = dir ? g_hb : g_hf;
    int myp = rg & 1;                       // my batch parity
    int bat = c * 2 + myp;                  // my batch (0..7)
    int uloc = rg >> 1;                     // unit-local 0..3

    // ---- W fragments (A operand, m16k16), one-time ----
    uint32_t afr[2][8][4];
#pragma unroll
    for (int mt = 0; mt < 2; mt++) {
        int tau = w * 2 + mt;
        int o1 = (myp)     * 128 + tau * 4 + uloc;   // gate rg&1   (row rg)
        int o2 = (myp + 2) * 128 + tau * 4 + uloc;   // gate rg&1+2 (row rg+8)
        const float* w1 = Whh + (size_t)o1 * H_;
        const float* w2 = Whh + (size_t)o2 * H_;
#pragma unroll
        for (int kt = 0; kt < 8; kt++) {
            int k = kt * 16 + c * 2;
            float2 p0 = *(const float2*)&w1[k];
            float2 p1 = *(const float2*)&w2[k];
            float2 p2 = *(const float2*)&w1[k + 8];
            float2 p3 = *(const float2*)&w2[k + 8];
            __half2 h0 = __floats2half2_rn(p0.x, p0.y);
            __half2 h1 = __floats2half2_rn(p1.x, p1.y);
            __half2 h2 = __floats2half2_rn(p2.x, p2.y);
            __half2 h3 = __floats2half2_rn(p3.x, p3.y);
            afr[mt][kt][0] = *(uint32_t*)&h0;
            afr[mt][kt][1] = *(uint32_t*)&h1;
            afr[mt][kt][2] = *(uint32_t*)&h2;
            afr[mt][kt][3] = *(uint32_t*)&h3;
        }
    }

    // zero h buffers
    for (int i = tid; i < 2 * H_ * NB; i += 512) ((__half*)sh)[i] = __float2half(0.f);

    // x prefetch: per m-tile 2 half2 (rows rg, rg+8 of the m16 tile; batches c*2, c*2+1)
    const size_t nbase = (size_t)(dir * G4 + w * 32);
    uint32_t xr[2][2];
    {
        int tt = dir ? (T_ - 1) : 0;
        size_t mo = (size_t)tt * B_ + b0 + c * 2;
#pragma unroll
        for (int mt = 0; mt < 2; mt++) {
            xr[mt][0] = *(const uint32_t*)&g_xg[(nbase + mt * 16 + rg)     * M_ + mo];
            xr[mt][1] = *(const uint32_t*)&g_xg[(nbase + mt * 16 + rg + 8) * M_ + mo];
        }
    }

    float cst[2] = {0.f, 0.f};
    __syncthreads();

    for (int s = 0; s < T_; ++s) {
        int tt = dir ? (T_ - 1 - s) : s;

        // D init = x preacts
        float d[2][4];
#pragma unroll
        for (int mt = 0; mt < 2; mt++) {
            float2 lo = __half22float2(*(__half2*)&xr[mt][0]);
            float2 hi = __half22float2(*(__half2*)&xr[mt][1]);
            d[mt][0] = lo.x; d[mt][1] = lo.y; d[mt][2] = hi.x; d[mt][3] = hi.y;
        }

        // B fragments (h), shared by both m-tiles
        uint32_t bfr[8][2];
#pragma unroll
        for (int kt = 0; kt < 8; kt++) {
            unsigned sb = (unsigned)__cvta_generic_to_shared(&sh[s & 1][kt * 16 + (l & 15)][0]);
            asm volatile("ldmatrix.sync.aligned.m8n8.x2.trans.shared.b16 {%0,%1}, [%2];"
                         : "=r"(bfr[kt][0]), "=r"(bfr[kt][1]) : "r"(sb));
        }
#pragma unroll
        for (int mt = 0; mt < 2; mt++)
#pragma unroll
            for (int kt = 0; kt < 8; kt++)
                asm volatile(
                    "mma.sync.aligned.m16n8k16.row.col.f32.f16.f16.f32 "
                    "{%0,%1,%2,%3},{%4,%5,%6,%7},{%8,%9},{%0,%1,%2,%3};"
                    : "+f"(d[mt][0]), "+f"(d[mt][1]), "+f"(d[mt][2]), "+f"(d[mt][3])
                    : "r"(afr[mt][kt][0]), "r"(afr[mt][kt][1]),
                      "r"(afr[mt][kt][2]), "r"(afr[mt][kt][3]),
                      "r"(bfr[kt][0]), "r"(bfr[kt][1]));

        // prefetch next x
        if (s + 1 < T_) {
            int tn = dir ? (T_ - 2 - s) : (s + 1);
            size_t mo = (size_t)tn * B_ + b0 + c * 2;
#pragma unroll
            for (int mt = 0; mt < 2; mt++) {
                xr[mt][0] = *(const uint32_t*)&g_xg[(nbase + mt * 16 + rg)     * M_ + mo];
                xr[mt][1] = *(const uint32_t*)&g_xg[(nbase + mt * 16 + rg + 8) * M_ + mo];
            }
        }

        // elementwise: rows rg/(rg+8) = gate pair {myp, myp+2} of unit uloc
#pragma unroll
        for (int mt = 0; mt < 2; mt++) {
            float alo_b0 = sig_t(d[mt][0]);
            float alo_b1 = sig_t(d[mt][1]);
            float ahi_b0 = myp ? sig_t(d[mt][2]) : tanh_t(d[mt][2]);
            float ahi_b1 = myp ? sig_t(d[mt][3]) : tanh_t(d[mt][3]);
            float mine_lo = myp ? alo_b1 : alo_b0;
            float mine_hi = myp ? ahi_b1 : ahi_b0;
            float send_lo = myp ? alo_b0 : alo_b1;
            float send_hi = myp ? ahi_b0 : ahi_b1;
            float rec_lo = __shfl_xor_sync(0xffffffffu, send_lo, 4);
            float rec_hi = __shfl_xor_sync(0xffffffffu, send_hi, 4);
            float ii = myp ? rec_lo  : mine_lo;
            float gg = myp ? rec_hi  : mine_hi;
            float ff = myp ? mine_lo : rec_lo;
            float oo = myp ? mine_hi : rec_hi;
            float cn = fmaf(ff, cst[mt], ii * gg);
            cst[mt] = cn;
            float hh = oo * tanh_t(cn);
            int unit = (w * 2 + mt) * 4 + uloc;
            sh[(s + 1) & 1][unit][bat] = __float2half_rn(hh);
            hout[((size_t)tt * B_ + b0 + bat) * H_ + unit] = hh;
        }
        __syncthreads();
    }
}

// ---------------- attention pooling + MLP head ----------------
__global__ __launch_bounds__(256) void attn_mlp(
    const float* __restrict__ attn_w, const float* __restrict__ attn_b,
    const float* __restrict__ fc1_w, const float* __restrict__ fc1_b,
    const float* __restrict__ fc2_w, const float* __restrict__ fc2_b,
    float* __restrict__ out) {
    __shared__ float aw[256];
    __shared__ float sl[512];
    __shared__ float red[256];
    __shared__ float sp[256];
    __shared__ float sh1[256];

    int b = blockIdx.x, tid = threadIdx.x;
    aw[tid] = attn_w[tid];
    __syncthreads();
    float ab = attn_b[0];

#pragma unroll
    for (int r = 0; r < 2; r++) {
        int t = tid + r * 256;
        const float4* pf = (const float4*)&g_hf[((size_t)t * B_ + b) * H_];
        const float4* pb = (const float4*)&g_hb[((size_t)t * B_ + b) * H_];
        const float4* wf = (const float4*)aw;
        const float4* wb = (const float4*)(aw + 128);
        float acc = 0.f;
#pragma unroll 8
        for (int qq = 0; qq < 32; qq++) {
            float4 a = pf[qq]; float4 w = wf[qq];
            acc += a.x * w.x + a.y * w.y + a.z * w.z + a.w * w.w;
        }
#pragma unroll 8
        for (int qq = 0; qq < 32; qq++) {
            float4 a = pb[qq]; float4 w = wb[qq];
            acc += a.x * w.x + a.y * w.y + a.z * w.z + a.w * w.w;
        }
        sl[t] = acc + ab;
    }
    __syncthreads();

    red[tid] = fmaxf(sl[tid], sl[tid + 256]);
    __syncthreads();
    for (int st = 128; st > 0; st >>= 1) {
        if (tid < st) red[tid] = fmaxf(red[tid], red[tid + st]);
        __syncthreads();
    }
    float mx = red[0];
    __syncthreads();
    float e0 = __expf(sl[tid] - mx), e1 = __expf(sl[tid + 256] - mx);
    sl[tid] = e0; sl[tid + 256] = e1;
    red[tid] = e0 + e1;
    __syncthreads();
    for (int st = 128; st > 0; st >>= 1) {
        if (tid < st) red[tid] += red[tid + st];
        __syncthreads();
    }
    float inv = 1.f / red[0];
    __syncthreads();

    {
        const float* src = (tid < 128) ? g_hf : g_hb;
        int u = tid & 127;
        float a0 = 0, a1 = 0, a2 = 0, a3 = 0;
        for (int t = 0; t < 512; t += 4) {
            a0 += sl[t    ] * src[((size_t)(t    ) * B_ + b) * H_ + u];
            a1 += sl[t + 1] * src[((size_t)(t + 1) * B_ + b) * H_ + u];
            a2 += sl[t + 2] * src[((size_t)(t + 2) * B_ + b) * H_ + u];
            a3 += sl[t + 3] * src[((size_t)(t + 3) * B_ + b) * H_ + u];
        }
        sp[tid] = (a0 + a1 + a2 + a3) * inv;
    }
    __syncthreads();

    {
        const float4* w = (const float4*)&fc1_w[(size_t)tid * 256];
        const float4* p = (const float4*)sp;
        float acc = fc1_b[tid];
#pragma unroll 8
        for (int qq = 0; qq < 64; qq++) {
            float4 a = p[qq]; float4 ww = w[qq];
            acc += a.x * ww.x + a.y * ww.y + a.z * ww.z + a.w * ww.w;
        }
        sh1[tid] = fmaxf(acc, 0.f);
    }
    __syncthreads();

    if (tid < 160) {
        int cc = tid >> 5, lane = tid & 31;
        float acc = 0.f;
        for (int qq = lane; qq < 256; qq += 32) acc += sh1[qq] * fc2_w[(size_t)cc * 256 + qq];
#pragma unroll
        for (int o = 16; o > 0; o >>= 1) acc += __shfl_down_sync(0xffffffffu, acc, o);
        if (lane == 0) out[b * C_ + cc] = acc + fc2_b[cc];
    }
}

// ---------------- launch ----------------
extern "C" void kernel_launch(void* const* d_in, const int* in_sizes, int n_in,
                              void* d_out, int out_size) {
    const float* x      = (const float*)d_in[0];
    const float* Wih_f  = (const float*)d_in[1];
    const float* Whh_f  = (const float*)d_in[2];
    const float* bih_f  = (const float*)d_in[3];
    const float* bhh_f  = (const float*)d_in[4];
    const float* Wih_b  = (const float*)d_in[5];
    const float* Whh_b  = (const float*)d_in[6];
    const float* bih_b  = (const float*)d_in[7];
    const float* bhh_b  = (const float*)d_in[8];
    const float* attn_w = (const float*)d_in[9];
    const float* attn_b = (const float*)d_in[10];
    const float* fc1_w  = (const float*)d_in[11];
    const float* fc1_b  = (const float*)d_in[12];
    const float* fc2_w  = (const float*)d_in[13];
    const float* fc2_b  = (const float*)d_in[14];
    float* out = (float*)d_out;

    prep_x<<<M_ / 2, 2 * KP>>>(x);
    prep_w<<<N_, KP>>>(Wih_f, Wih_b);
    gemm_hmma<<<dim3(N_ / BN, M_ / BM), 256>>>(bih_f, bhh_f, bih_b, bhh_b);

    lstm_scan_mma<<<32, 512>>>(Whh_f, Whh_b);

    attn_mlp<<<B_, 256>>>(attn_w, attn_b, fc1_w, fc1_b, fc2_w, fc2_b, out);
}